// round 6
// baseline (speedup 1.0000x reference)
#include <cuda_runtime.h>
#include <cuda_bf16.h>
#include <math.h>
#include <stdint.h>

#define NB    4
#define NC    256
#define NTOK  4096
#define NHEAD 4
#define DH    32
#define HID   128
#define NQKV  384
#define CPG   8

// -------- scratch --------
__device__ float g_qkv[(size_t)NB * NQKV * NTOK];   // [b][o][n]  rna-tf32 values
__device__ float g_att[(size_t)NB * HID * NTOK];    // [b][h*32+f][n] rna-tf32 values
__device__ float g_xn [(size_t)NB * NC * NTOK];     // normalized x, rna-tf32

// ---------- helpers ----------
__device__ __forceinline__ uint32_t f2tf(float f) {
    uint32_t u; asm("cvt.rna.tf32.f32 %0, %1;" : "=r"(u) : "f"(f)); return u;
}
__device__ __forceinline__ float rtf(float f) { return __uint_as_float(f2tf(f)); }
__device__ __forceinline__ float ex2(float x) {
    float y; asm("ex2.approx.ftz.f32 %0, %1;" : "=f"(y) : "f"(x)); return y;
}
__device__ __forceinline__ void mma_tf32(float c[4], const uint32_t a[4], uint32_t b0, uint32_t b1) {
    asm volatile("mma.sync.aligned.m16n8k8.row.col.f32.tf32.tf32.f32 "
                 "{%0,%1,%2,%3}, {%4,%5,%6,%7}, {%8,%9}, {%0,%1,%2,%3};"
                 : "+f"(c[0]), "+f"(c[1]), "+f"(c[2]), "+f"(c[3])
                 : "r"(a[0]), "r"(a[1]), "r"(a[2]), "r"(a[3]), "r"(b0), "r"(b1));
}
__device__ __forceinline__ void cpa16(uint32_t dst, const void* src) {
    asm volatile("cp.async.ca.shared.global [%0], [%1], 16;" :: "r"(dst), "l"(src));
}
#define CPA_COMMIT() asm volatile("cp.async.commit_group;")

// ================= GroupNorm: stats + write normalized x (rna-tf32) =================
__global__ void __launch_bounds__(256) k_gnstats(const float* __restrict__ x,
                                                 const float* __restrict__ gw,
                                                 const float* __restrict__ gb)
{
    const int b = blockIdx.x >> 5;
    const int g = blockIdx.x & 31;
    const size_t base = ((size_t)(b * NC + g * CPG)) * NTOK;
    const float4* p4 = (const float4*)(x + base);
    float4* o4 = (float4*)(g_xn + base);
    float s = 0.f, s2 = 0.f;
    for (int i = threadIdx.x; i < 8192; i += 256) {
        float4 v = p4[i];
        s  += (v.x + v.y) + (v.z + v.w);
        s2 += v.x * v.x + v.y * v.y + v.z * v.z + v.w * v.w;
    }
    #pragma unroll
    for (int off = 16; off; off >>= 1) {
        s  += __shfl_xor_sync(0xffffffffu, s,  off);
        s2 += __shfl_xor_sync(0xffffffffu, s2, off);
    }
    __shared__ float ws[8], ws2[8];
    __shared__ float al8[CPG], be8[CPG];
    const int w = threadIdx.x >> 5;
    if ((threadIdx.x & 31) == 0) { ws[w] = s; ws2[w] = s2; }
    __syncthreads();
    if (threadIdx.x < CPG) {
        float t = 0.f, t2 = 0.f;
        #pragma unroll
        for (int i = 0; i < 8; i++) { t += ws[i]; t2 += ws2[i]; }
        float mean = t * (1.f / 32768.f);
        float var  = t2 * (1.f / 32768.f) - mean * mean;
        float sr = rsqrtf(var + 1e-5f);
        int c = g * CPG + threadIdx.x;
        float a = gw[c] * sr;
        al8[threadIdx.x] = a;
        be8[threadIdx.x] = gb[c] - mean * a;
    }
    __syncthreads();
    for (int i = threadIdx.x; i < 8192; i += 256) {
        int cl = i >> 10;
        float a = al8[cl], bb = be8[cl];
        float4 v = p4[i];
        o4[i] = make_float4(rtf(fmaf(v.x, a, bb)), rtf(fmaf(v.y, a, bb)),
                            rtf(fmaf(v.z, a, bb)), rtf(fmaf(v.w, a, bb)));
    }
}

// ================= pipelined tf32 GEMM =================
template<int MTOT, int KTOT, bool ROUND, bool BIASED>
__global__ void __launch_bounds__(256) k_gemm(const float* __restrict__ A,
                                              const float* __restrict__ Bg,
                                              float* __restrict__ Cg,
                                              const float* __restrict__ bias)
{
    constexpr int NK = KTOT / 32;
    const int b  = blockIdx.z;
    const int m0 = blockIdx.y * 128;
    const int n0 = blockIdx.x * 64;
    __shared__ float As[128][36];
    __shared__ float Xs[2][32][72];
    const float* Bb = Bg + (size_t)b * KTOT * NTOK;
    const int tid = threadIdx.x, w = tid >> 5, lane = tid & 31;
    const int g = lane >> 2, t = lane & 3;
    const int wm = (w >> 1) * 32, wn = (w & 1) * 32;
    const uint32_t xsbase = (uint32_t)__cvta_generic_to_shared(&Xs[0][0][0]);
    const int kcA = tid >> 4, ncA = (tid & 15) << 2;
    const int kcB = kcA + 16;

    float4 ar[2][4];
    float acc[2][4][4] = {};

    cpa16(xsbase + kcA * 288 + ncA * 4, Bb + (size_t)kcA * NTOK + n0 + ncA);
    cpa16(xsbase + kcB * 288 + ncA * 4, Bb + (size_t)kcB * NTOK + n0 + ncA);
    CPA_COMMIT();
    #pragma unroll
    for (int i = 0; i < 4; i++) {
        int id = tid + 256 * i, m = id >> 3, c = (id & 7) << 2;
        ar[0][i] = *(const float4*)(A + (size_t)(m0 + m) * KTOT + c);
    }

    #pragma unroll
    for (int k = 0; k < NK; k++) {
        __syncthreads();
        #pragma unroll
        for (int i = 0; i < 4; i++) {
            int id = tid + 256 * i, m = id >> 3, c = (id & 7) << 2;
            float4 v = ar[k & 1][i];
            As[m][c] = rtf(v.x); As[m][c + 1] = rtf(v.y);
            As[m][c + 2] = rtf(v.z); As[m][c + 3] = rtf(v.w);
        }
        if (k + 1 < NK) {
            uint32_t bo = xsbase + ((k + 1) & 1) * 9216;
            cpa16(bo + kcA * 288 + ncA * 4, Bb + (size_t)((k + 1) * 32 + kcA) * NTOK + n0 + ncA);
            cpa16(bo + kcB * 288 + ncA * 4, Bb + (size_t)((k + 1) * 32 + kcB) * NTOK + n0 + ncA);
            CPA_COMMIT();
            #pragma unroll
            for (int i = 0; i < 4; i++) {
                int id = tid + 256 * i, m = id >> 3, c = (id & 7) << 2;
                ar[(k + 1) & 1][i] = *(const float4*)(A + (size_t)(m0 + m) * KTOT + (k + 1) * 32 + c);
            }
            asm volatile("cp.async.wait_group 1;");
        } else {
            asm volatile("cp.async.wait_group 0;");
        }
        __syncthreads();
        const float (*X)[72] = Xs[k & 1];
        #pragma unroll
        for (int ks = 0; ks < 4; ks++) {
            uint32_t a[2][4];
            #pragma unroll
            for (int mf = 0; mf < 2; mf++) {
                int r = wm + 16 * mf + g;
                a[mf][0] = __float_as_uint(As[r    ][8 * ks + t]);
                a[mf][1] = __float_as_uint(As[r + 8][8 * ks + t]);
                a[mf][2] = __float_as_uint(As[r    ][8 * ks + t + 4]);
                a[mf][3] = __float_as_uint(As[r + 8][8 * ks + t + 4]);
            }
            #pragma unroll
            for (int nf = 0; nf < 4; nf++) {
                uint32_t b0 = __float_as_uint(X[8 * ks + t    ][wn + 8 * nf + g]);
                uint32_t b1 = __float_as_uint(X[8 * ks + t + 4][wn + 8 * nf + g]);
                mma_tf32(acc[0][nf], a[0], b0, b1);
                mma_tf32(acc[1][nf], a[1], b0, b1);
            }
        }
    }

    float* Cb = Cg + (size_t)b * MTOT * NTOK;
    #pragma unroll
    for (int mf = 0; mf < 2; mf++) {
        int row = m0 + wm + 16 * mf + g;
        float bv0 = BIASED ? bias[row]     : 0.f;
        float bv8 = BIASED ? bias[row + 8] : 0.f;
        #pragma unroll
        for (int nf = 0; nf < 4; nf++) {
            int col = n0 + wn + 8 * nf + 2 * t;
            float v0 = acc[mf][nf][0] + bv0, v1 = acc[mf][nf][1] + bv0;
            float v2 = acc[mf][nf][2] + bv8, v3 = acc[mf][nf][3] + bv8;
            if (ROUND) { v0 = rtf(v0); v1 = rtf(v1); v2 = rtf(v2); v3 = rtf(v3); }
            *(float2*)(Cb + (size_t)row * NTOK + col)       = make_float2(v0, v1);
            *(float2*)(Cb + (size_t)(row + 8) * NTOK + col) = make_float2(v2, v3);
        }
    }
}

// ================= Flash attention: depth-3 cp.async pipeline =================
// dyn SMEM (bytes):
//  buf(i) @ i*17920, i=0..2 :  K 32x72 f32 (9216) + V 32x68 f32 (8704)
//  P @ 53760 : 8 warps x [16][36] f32 (2304 each) = 18432   -> total 72192
//  Qs @ 0 : 128x36 f32 = 18432 (prologue/epilogue only, temporally aliased)
#define QT 128
#define KT 64
#define NTILES (NTOK / KT)
#define BUFSTRIDE 17920u
#define SMA_BYTES 72192
__global__ void __launch_bounds__(256, 2) k_attn()
{
    extern __shared__ __align__(16) char smraw[];
    float (*Qs)[36] = (float(*)[36])smraw;
    const uint32_t smbase = (uint32_t)__cvta_generic_to_shared(smraw);

    const int b  = blockIdx.z, h = blockIdx.y;
    const int n0 = blockIdx.x * QT;
    const int tid  = threadIdx.x;
    const int w    = tid >> 5;
    const int lane = tid & 31;
    const int grp  = lane >> 2;
    const int tg   = lane & 3;

    const float* qb = g_qkv + ((size_t)b * NQKV + h * DH) * NTOK;
    const float* kb = qb + (size_t)HID * NTOK;
    const float* vb = qb + (size_t)2 * HID * NTOK;

    const float qscale = 0.17677669529663687f * 1.4426950408889634f; // SCALE*log2(e)

    // ---- prologue: stage Q, build fragments ----
    #pragma unroll
    for (int i = 0; i < 4; i++) {
        int idx4 = tid + 256 * i;
        int f  = idx4 >> 5;
        int nc = (idx4 & 31) << 2;
        float4 v = *(const float4*)(qb + (size_t)f * NTOK + n0 + nc);
        Qs[nc + 0][f] = rtf(v.x * qscale);
        Qs[nc + 1][f] = rtf(v.y * qscale);
        Qs[nc + 2][f] = rtf(v.z * qscale);
        Qs[nc + 3][f] = rtf(v.w * qscale);
    }
    __syncthreads();
    const int qrow = w * 16 + grp;
    uint32_t qa[4][4];
    #pragma unroll
    for (int ks = 0; ks < 4; ks++) {
        qa[ks][0] = __float_as_uint(Qs[qrow    ][8 * ks + tg]);
        qa[ks][1] = __float_as_uint(Qs[qrow + 8][8 * ks + tg]);
        qa[ks][2] = __float_as_uint(Qs[qrow    ][8 * ks + tg + 4]);
        qa[ks][3] = __float_as_uint(Qs[qrow + 8][8 * ks + tg + 4]);
    }
    __syncthreads();   // Q-frag reads done before K/V staging overwrites alias

    // staging offsets within one buffer
    const int sf0 = tid >> 4;
    const int sj0 = (tid & 15) << 2;
    const int sf1 = sf0 + 16;
    const uint32_t kd0 = (uint32_t)(sf0 * 72 + sj0) * 4;
    const uint32_t kd1 = (uint32_t)(sf1 * 72 + sj0) * 4;
    const uint32_t vd0 = 9216u + (uint32_t)(sf0 * 68 + sj0) * 4;
    const uint32_t vd1 = 9216u + (uint32_t)(sf1 * 68 + sj0) * 4;
    float (*Pw)[36] = (float(*)[36])(smraw + 53760 + w * 2304);

    float o[4][4] = {};
    float m0r = -1e30f, m1r = -1e30f;
    float l0 = 0.f, l1 = 0.f;

    // prefetch tiles 0,1 -> buffers 0,1 (separate commit groups)
    #pragma unroll
    for (int p = 0; p < 2; p++) {
        const uint32_t bo = smbase + p * BUFSTRIDE;
        const int jn = p * KT;
        cpa16(bo + kd0, kb + (size_t)sf0 * NTOK + jn + sj0);
        cpa16(bo + kd1, kb + (size_t)sf1 * NTOK + jn + sj0);
        cpa16(bo + vd0, vb + (size_t)sf0 * NTOK + jn + sj0);
        cpa16(bo + vd1, vb + (size_t)sf1 * NTOK + jn + sj0);
        CPA_COMMIT();
    }

    int cur = 0, wb = 2;   // current read buffer, next write buffer
    for (int tIdx = 0; tIdx < NTILES; tIdx++) {
        __syncthreads();   // all warps done reading buf[wb] (tile tIdx-1 readers flushed)
        if (tIdx + 2 < NTILES) {
            const uint32_t bo = smbase + wb * BUFSTRIDE;
            const int jn = (tIdx + 2) * KT;
            cpa16(bo + kd0, kb + (size_t)sf0 * NTOK + jn + sj0);
            cpa16(bo + kd1, kb + (size_t)sf1 * NTOK + jn + sj0);
            cpa16(bo + vd0, vb + (size_t)sf0 * NTOK + jn + sj0);
            cpa16(bo + vd1, vb + (size_t)sf1 * NTOK + jn + sj0);
            CPA_COMMIT();
            asm volatile("cp.async.wait_group 2;");
        } else if (tIdx + 1 < NTILES) {
            asm volatile("cp.async.wait_group 1;");
        } else {
            asm volatile("cp.async.wait_group 0;");
        }

        const float (*Ks)[72] = (const float(*)[72])(smraw + cur * BUFSTRIDE);
        const float (*Vs)[68] = (const float(*)[68])(smraw + cur * BUFSTRIDE + 9216);
        wb = cur;
        cur = (cur == 2) ? 0 : cur + 1;

        // ---- S = Q K^T (16q x 64k per warp) ----
        float sc[8][4];
        #pragma unroll
        for (int nt = 0; nt < 8; nt++) {
            sc[nt][0] = sc[nt][1] = sc[nt][2] = sc[nt][3] = 0.f;
            #pragma unroll
            for (int ks = 0; ks < 4; ks++) {
                uint32_t b0 = __float_as_uint(Ks[8 * ks + tg    ][8 * nt + grp]);
                uint32_t b1 = __float_as_uint(Ks[8 * ks + tg + 4][8 * nt + grp]);
                mma_tf32(sc[nt], qa[ks], b0, b1);
            }
        }

        // ---- online softmax (exp2 domain) ----
        float mt0 = -1e30f, mt1 = -1e30f;
        #pragma unroll
        for (int nt = 0; nt < 8; nt++) {
            mt0 = fmaxf(mt0, fmaxf(sc[nt][0], sc[nt][1]));
            mt1 = fmaxf(mt1, fmaxf(sc[nt][2], sc[nt][3]));
        }
        mt0 = fmaxf(mt0, __shfl_xor_sync(0xffffffffu, mt0, 1));
        mt0 = fmaxf(mt0, __shfl_xor_sync(0xffffffffu, mt0, 2));
        mt1 = fmaxf(mt1, __shfl_xor_sync(0xffffffffu, mt1, 1));
        mt1 = fmaxf(mt1, __shfl_xor_sync(0xffffffffu, mt1, 2));
        float mn0 = fmaxf(m0r, mt0), mn1 = fmaxf(m1r, mt1);
        float c0 = ex2(m0r - mn0), c1 = ex2(m1r - mn1);
        m0r = mn0; m1r = mn1;
        l0 *= c0; l1 *= c1;
        #pragma unroll
        for (int nf = 0; nf < 4; nf++) {
            o[nf][0] *= c0; o[nf][1] *= c0;
            o[nf][2] *= c1; o[nf][3] *= c1;
        }
        float rs0 = 0.f, rs1 = 0.f;
        #pragma unroll
        for (int nt = 0; nt < 8; nt++) {
            float p0 = ex2(sc[nt][0] - mn0);
            float p1 = ex2(sc[nt][1] - mn0);
            float p2 = ex2(sc[nt][2] - mn1);
            float p3 = ex2(sc[nt][3] - mn1);
            rs0 += p0 + p1; rs1 += p2 + p3;
            sc[nt][0] = p0; sc[nt][1] = p1; sc[nt][2] = p2; sc[nt][3] = p3;
        }
        rs0 += __shfl_xor_sync(0xffffffffu, rs0, 1);
        rs0 += __shfl_xor_sync(0xffffffffu, rs0, 2);
        rs1 += __shfl_xor_sync(0xffffffffu, rs1, 1);
        rs1 += __shfl_xor_sync(0xffffffffu, rs1, 2);
        l0 += rs0; l1 += rs1;

        // ---- O += P V : P via per-warp SMEM, two 32-key halves ----
        #pragma unroll
        for (int h2 = 0; h2 < 2; h2++) {
            #pragma unroll
            for (int ntl = 0; ntl < 4; ntl++) {
                int nt = 4 * h2 + ntl;
                *(float2*)&Pw[grp    ][8 * ntl + 2 * tg] = make_float2(sc[nt][0], sc[nt][1]);
                *(float2*)&Pw[grp + 8][8 * ntl + 2 * tg] = make_float2(sc[nt][2], sc[nt][3]);
            }
            __syncwarp();
            #pragma unroll
            for (int kkl = 0; kkl < 4; kkl++) {
                int kk = 4 * h2 + kkl;
                uint32_t pa[4];
                pa[0] = __float_as_uint(Pw[grp    ][8 * kkl + tg]);
                pa[1] = __float_as_uint(Pw[grp + 8][8 * kkl + tg]);
                pa[2] = __float_as_uint(Pw[grp    ][8 * kkl + tg + 4]);
                pa[3] = __float_as_uint(Pw[grp + 8][8 * kkl + tg + 4]);
                #pragma unroll
                for (int nf = 0; nf < 4; nf++) {
                    uint32_t b0 = __float_as_uint(Vs[8 * nf + grp][8 * kk + tg]);
                    uint32_t b1 = __float_as_uint(Vs[8 * nf + grp][8 * kk + tg + 4]);
                    mma_tf32(o[nf], pa, b0, b1);
                }
            }
            __syncwarp();
        }
    }
    __syncthreads();

    // ---- epilogue ----
    float inv0 = 1.0f / l0, inv1 = 1.0f / l1;
    #pragma unroll
    for (int nf = 0; nf < 4; nf++) {
        Qs[qrow    ][8 * nf + 2 * tg    ] = rtf(o[nf][0] * inv0);
        Qs[qrow    ][8 * nf + 2 * tg + 1] = rtf(o[nf][1] * inv0);
        Qs[qrow + 8][8 * nf + 2 * tg    ] = rtf(o[nf][2] * inv1);
        Qs[qrow + 8][8 * nf + 2 * tg + 1] = rtf(o[nf][3] * inv1);
    }
    __syncthreads();
    float* ob = g_att + ((size_t)b * HID + h * DH) * NTOK;
    #pragma unroll
    for (int i = 0; i < 4; i++) {
        int idx4 = tid + 256 * i;
        int f  = idx4 >> 5;
        int nc = (idx4 & 31) << 2;
        *(float4*)(ob + (size_t)f * NTOK + n0 + nc) =
            make_float4(Qs[nc + 0][f], Qs[nc + 1][f], Qs[nc + 2][f], Qs[nc + 3][f]);
    }
}

// ================= launch =================
extern "C" void kernel_launch(void* const* d_in, const int* in_sizes, int n_in,
                              void* d_out, int out_size)
{
    const float* x    = (const float*)d_in[0];
    const float* gw   = (const float*)d_in[1];
    const float* gb   = (const float*)d_in[2];
    const float* wqkv = (const float*)d_in[3];
    const float* wout = (const float*)d_in[4];
    const float* bout = (const float*)d_in[5];
    float* out = (float*)d_out;

    float* qkv = nullptr; cudaGetSymbolAddress((void**)&qkv, g_qkv);
    float* att = nullptr; cudaGetSymbolAddress((void**)&att, g_att);
    float* xn  = nullptr; cudaGetSymbolAddress((void**)&xn,  g_xn);

    cudaFuncSetAttribute(k_attn, cudaFuncAttributeMaxDynamicSharedMemorySize, SMA_BYTES);

    k_gnstats<<<NB * 32, 256>>>(x, gw, gb);
    k_gemm<NQKV, NC, true, false><<<dim3(64, 3, NB), 256>>>(wqkv, xn, qkv, nullptr);
    k_attn<<<dim3(NTOK / QT, NHEAD, NB), 256, SMA_BYTES>>>();
    k_gemm<NC, HID, false, true><<<dim3(64, 2, NB), 256>>>(wout, att, out, bout);
}

// round 7
// speedup vs baseline: 1.5430x; 1.5430x over previous
#include <cuda_runtime.h>
#include <cuda_fp16.h>
#include <math.h>
#include <stdint.h>

#define NB    4
#define NC    256
#define NTOK  4096
#define NHEAD 4
#define DH    32
#define HID   128
#define NQKV  384
#define CPG   8

// Q pre-scale: DH^-0.5 * log2(e)
#define QSCL 0.2550662672f

// -------- scratch --------
__device__ __half g_q[(size_t)NB * NHEAD * NTOK * DH];   // [b][h][tok][f] token-major, pre-scaled
__device__ __half g_k[(size_t)NB * NHEAD * NTOK * DH];   // [b][h][tok][f] token-major
__device__ __half g_v[(size_t)NB * HID * NTOK];          // [b][f][tok]   f-major
__device__ float  g_att[(size_t)NB * HID * NTOK];        // fp32 f-major (rna-tf32 values)
__device__ float  g_xn [(size_t)NB * NC * NTOK];         // normalized x, rna-tf32

// ---------- helpers ----------
__device__ __forceinline__ uint32_t f2tf(float f) {
    uint32_t u; asm("cvt.rna.tf32.f32 %0, %1;" : "=r"(u) : "f"(f)); return u;
}
__device__ __forceinline__ float rtf(float f) { return __uint_as_float(f2tf(f)); }
__device__ __forceinline__ float ex2(float x) {
    float y; asm("ex2.approx.ftz.f32 %0, %1;" : "=f"(y) : "f"(x)); return y;
}
__device__ __forceinline__ void mma_tf32(float c[4], const uint32_t a[4], uint32_t b0, uint32_t b1) {
    asm volatile("mma.sync.aligned.m16n8k8.row.col.f32.tf32.tf32.f32 "
                 "{%0,%1,%2,%3}, {%4,%5,%6,%7}, {%8,%9}, {%0,%1,%2,%3};"
                 : "+f"(c[0]), "+f"(c[1]), "+f"(c[2]), "+f"(c[3])
                 : "r"(a[0]), "r"(a[1]), "r"(a[2]), "r"(a[3]), "r"(b0), "r"(b1));
}
__device__ __forceinline__ void mma_f16(float c[4], const uint32_t a[4], uint32_t b0, uint32_t b1) {
    asm volatile("mma.sync.aligned.m16n8k16.row.col.f32.f16.f16.f32 "
                 "{%0,%1,%2,%3}, {%4,%5,%6,%7}, {%8,%9}, {%0,%1,%2,%3};"
                 : "+f"(c[0]), "+f"(c[1]), "+f"(c[2]), "+f"(c[3])
                 : "r"(a[0]), "r"(a[1]), "r"(a[2]), "r"(a[3]), "r"(b0), "r"(b1));
}
__device__ __forceinline__ void cpa16(uint32_t dst, const void* src) {
    asm volatile("cp.async.ca.shared.global [%0], [%1], 16;" :: "r"(dst), "l"(src));
}
#define CPA_COMMIT() asm volatile("cp.async.commit_group;")

// ================= GroupNorm: stats + write normalized x (rna-tf32) =================
__global__ void __launch_bounds__(256) k_gnstats(const float* __restrict__ x,
                                                 const float* __restrict__ gw,
                                                 const float* __restrict__ gb)
{
    const int b = blockIdx.x >> 5;
    const int g = blockIdx.x & 31;
    const size_t base = ((size_t)(b * NC + g * CPG)) * NTOK;
    const float4* p4 = (const float4*)(x + base);
    float4* o4 = (float4*)(g_xn + base);
    float s = 0.f, s2 = 0.f;
    for (int i = threadIdx.x; i < 8192; i += 256) {
        float4 v = p4[i];
        s  += (v.x + v.y) + (v.z + v.w);
        s2 += v.x * v.x + v.y * v.y + v.z * v.z + v.w * v.w;
    }
    #pragma unroll
    for (int off = 16; off; off >>= 1) {
        s  += __shfl_xor_sync(0xffffffffu, s,  off);
        s2 += __shfl_xor_sync(0xffffffffu, s2, off);
    }
    __shared__ float ws[8], ws2[8];
    __shared__ float al8[CPG], be8[CPG];
    const int w = threadIdx.x >> 5;
    if ((threadIdx.x & 31) == 0) { ws[w] = s; ws2[w] = s2; }
    __syncthreads();
    if (threadIdx.x < CPG) {
        float t = 0.f, t2 = 0.f;
        #pragma unroll
        for (int i = 0; i < 8; i++) { t += ws[i]; t2 += ws2[i]; }
        float mean = t * (1.f / 32768.f);
        float var  = t2 * (1.f / 32768.f) - mean * mean;
        float sr = rsqrtf(var + 1e-5f);
        int c = g * CPG + threadIdx.x;
        float a = gw[c] * sr;
        al8[threadIdx.x] = a;
        be8[threadIdx.x] = gb[c] - mean * a;
    }
    __syncthreads();
    for (int i = threadIdx.x; i < 8192; i += 256) {
        int cl = i >> 10;
        float a = al8[cl], bb = be8[cl];
        float4 v = p4[i];
        o4[i] = make_float4(rtf(fmaf(v.x, a, bb)), rtf(fmaf(v.y, a, bb)),
                            rtf(fmaf(v.z, a, bb)), rtf(fmaf(v.w, a, bb)));
    }
}

// ================= pipelined tf32 GEMM =================
// OMODE 0: fp32 output + bias (out projection). OMODE 1: QKV fp16 output,
// blockIdx.y selects 0=Q(token-major, pre-scaled) 1=K(token-major) 2=V(f-major).
template<int MTOT, int KTOT, int OMODE>
__global__ void __launch_bounds__(256) k_gemm(const float* __restrict__ A,
                                              const float* __restrict__ Bg,
                                              float* __restrict__ Cg,
                                              const float* __restrict__ bias)
{
    constexpr int NK = KTOT / 32;
    const int b  = blockIdx.z;
    const int m0 = blockIdx.y * 128;
    const int n0 = blockIdx.x * 64;
    __shared__ float As[128][36];
    __shared__ float Xs[2][32][72];
    const float* Bb = Bg + (size_t)b * KTOT * NTOK;
    const int tid = threadIdx.x, w = tid >> 5, lane = tid & 31;
    const int g = lane >> 2, t = lane & 3;
    const int wm = (w >> 1) * 32, wn = (w & 1) * 32;
    const uint32_t xsbase = (uint32_t)__cvta_generic_to_shared(&Xs[0][0][0]);
    const int kcA = tid >> 4, ncA = (tid & 15) << 2;
    const int kcB = kcA + 16;

    float4 ar[2][4];
    float acc[2][4][4] = {};

    cpa16(xsbase + kcA * 288 + ncA * 4, Bb + (size_t)kcA * NTOK + n0 + ncA);
    cpa16(xsbase + kcB * 288 + ncA * 4, Bb + (size_t)kcB * NTOK + n0 + ncA);
    CPA_COMMIT();
    #pragma unroll
    for (int i = 0; i < 4; i++) {
        int id = tid + 256 * i, m = id >> 3, c = (id & 7) << 2;
        ar[0][i] = *(const float4*)(A + (size_t)(m0 + m) * KTOT + c);
    }

    #pragma unroll
    for (int k = 0; k < NK; k++) {
        __syncthreads();
        #pragma unroll
        for (int i = 0; i < 4; i++) {
            int id = tid + 256 * i, m = id >> 3, c = (id & 7) << 2;
            float4 v = ar[k & 1][i];
            As[m][c] = rtf(v.x); As[m][c + 1] = rtf(v.y);
            As[m][c + 2] = rtf(v.z); As[m][c + 3] = rtf(v.w);
        }
        if (k + 1 < NK) {
            uint32_t bo = xsbase + ((k + 1) & 1) * 9216;
            cpa16(bo + kcA * 288 + ncA * 4, Bb + (size_t)((k + 1) * 32 + kcA) * NTOK + n0 + ncA);
            cpa16(bo + kcB * 288 + ncA * 4, Bb + (size_t)((k + 1) * 32 + kcB) * NTOK + n0 + ncA);
            CPA_COMMIT();
            #pragma unroll
            for (int i = 0; i < 4; i++) {
                int id = tid + 256 * i, m = id >> 3, c = (id & 7) << 2;
                ar[(k + 1) & 1][i] = *(const float4*)(A + (size_t)(m0 + m) * KTOT + (k + 1) * 32 + c);
            }
            asm volatile("cp.async.wait_group 1;");
        } else {
            asm volatile("cp.async.wait_group 0;");
        }
        __syncthreads();
        const float (*X)[72] = Xs[k & 1];
        #pragma unroll
        for (int ks = 0; ks < 4; ks++) {
            uint32_t a[2][4];
            #pragma unroll
            for (int mf = 0; mf < 2; mf++) {
                int r = wm + 16 * mf + g;
                a[mf][0] = __float_as_uint(As[r    ][8 * ks + t]);
                a[mf][1] = __float_as_uint(As[r + 8][8 * ks + t]);
                a[mf][2] = __float_as_uint(As[r    ][8 * ks + t + 4]);
                a[mf][3] = __float_as_uint(As[r + 8][8 * ks + t + 4]);
            }
            #pragma unroll
            for (int nf = 0; nf < 4; nf++) {
                uint32_t b0 = __float_as_uint(X[8 * ks + t    ][wn + 8 * nf + g]);
                uint32_t b1 = __float_as_uint(X[8 * ks + t + 4][wn + 8 * nf + g]);
                mma_tf32(acc[0][nf], a[0], b0, b1);
                mma_tf32(acc[1][nf], a[1], b0, b1);
            }
        }
    }

    if (OMODE == 0) {
        float* Cb = Cg + (size_t)b * MTOT * NTOK;
        #pragma unroll
        for (int mf = 0; mf < 2; mf++) {
            int row = m0 + wm + 16 * mf + g;
            float bv0 = bias[row], bv8 = bias[row + 8];
            #pragma unroll
            for (int nf = 0; nf < 4; nf++) {
                int col = n0 + wn + 8 * nf + 2 * t;
                *(float2*)(Cb + (size_t)row * NTOK + col) =
                    make_float2(acc[mf][nf][0] + bv0, acc[mf][nf][1] + bv0);
                *(float2*)(Cb + (size_t)(row + 8) * NTOK + col) =
                    make_float2(acc[mf][nf][2] + bv8, acc[mf][nf][3] + bv8);
            }
        }
    } else {
        const int sel = blockIdx.y;          // 0=Q 1=K 2=V
        #pragma unroll
        for (int mf = 0; mf < 2; mf++) {
            int row = wm + 16 * mf + g;      // 0..127 within tile; f=row&31 in 0..23
            #pragma unroll
            for (int nf = 0; nf < 4; nf++) {
                int col = n0 + wn + 8 * nf + 2 * t;
                float v0 = acc[mf][nf][0], v1 = acc[mf][nf][1];
                float v2 = acc[mf][nf][2], v3 = acc[mf][nf][3];
                if (sel == 0) { v0 *= QSCL; v1 *= QSCL; v2 *= QSCL; v3 *= QSCL; }
                if (sel < 2) {
                    __half* base = (sel == 0 ? g_q : g_k)
                        + ((size_t)(b * NHEAD + (row >> 5)) * NTOK + col) * DH + (row & 31);
                    base[0]      = __float2half_rn(v0);
                    base[DH]     = __float2half_rn(v1);
                    base[8]      = __float2half_rn(v2);
                    base[DH + 8] = __float2half_rn(v3);
                } else {
                    *(__half2*)&g_v[((size_t)(b * HID + row)) * NTOK + col] =
                        __floats2half2_rn(v0, v1);
                    *(__half2*)&g_v[((size_t)(b * HID + row + 8)) * NTOK + col] =
                        __floats2half2_rn(v2, v3);
                }
            }
        }
    }
}

// ================= Flash attention: fp16 m16n8k16, depth-3 cp.async =================
// dyn SMEM (bytes):
//  buf(i) @ i*9728, i=0..2 :  K [64 key][40f] half (5120) + V [32f][72 key] half (4608)
//  P @ 29184 : 8 warps x [16][72] half (2304 each) = 18432   -> total 47616
//  Qs @ 0 : [128 tok][40 f] half = 10240 (prologue alias)
//  Ofs @ 0 : [32 f][132 tok] float = 16896 (epilogue alias)
#define QT 128
#define KT 64
#define NTILES (NTOK / KT)
#define BUFSTRIDE 9728u
#define SMA_BYTES 47616
__global__ void __launch_bounds__(256, 3) k_attn()
{
    extern __shared__ __align__(16) char smraw[];
    __half (*Qs)[40] = (__half(*)[40])smraw;
    const uint32_t smbase = (uint32_t)__cvta_generic_to_shared(smraw);

    const int b  = blockIdx.z, h = blockIdx.y;
    const int n0 = blockIdx.x * QT;
    const int tid  = threadIdx.x;
    const int w    = tid >> 5;
    const int lane = tid & 31;
    const int grp  = lane >> 2;
    const int tg   = lane & 3;

    const __half* qg = g_q + (size_t)(b * NHEAD + h) * NTOK * DH;
    const __half* kg = g_k + (size_t)(b * NHEAD + h) * NTOK * DH;
    const __half* vg = g_v + (size_t)(b * HID + h * DH) * NTOK;

    // ---- prologue: stage Q tile [128 tok][32 f] (token-major, pre-scaled) ----
    #pragma unroll
    for (int i = 0; i < 2; i++) {
        int chunk = tid + 256 * i;           // 512 chunks of 16B
        int tok = chunk >> 2;
        int fc  = (chunk & 3) * 8;           // halves
        cpa16(smbase + (uint32_t)(tok * 80 + fc * 2), qg + (size_t)(n0 + tok) * DH + fc);
    }
    CPA_COMMIT();
    asm volatile("cp.async.wait_group 0;");
    __syncthreads();

    const int qrow = w * 16 + grp;
    uint32_t qa[2][4];
    #pragma unroll
    for (int ks = 0; ks < 2; ks++) {
        qa[ks][0] = *(const uint32_t*)&Qs[qrow    ][16 * ks + 2 * tg];
        qa[ks][1] = *(const uint32_t*)&Qs[qrow + 8][16 * ks + 2 * tg];
        qa[ks][2] = *(const uint32_t*)&Qs[qrow    ][16 * ks + 2 * tg + 8];
        qa[ks][3] = *(const uint32_t*)&Qs[qrow + 8][16 * ks + 2 * tg + 8];
    }
    __syncthreads();   // Q reads done before K/V staging overwrites alias

    // staging coords (1 cp.async each for K and V per tile)
    const int kkey = tid >> 2;               // 0..63
    const int kfc  = (tid & 3) * 8;          // f chunk (halves)
    const int vf   = tid >> 3;               // 0..31
    const int vkc  = (tid & 7) * 8;          // key chunk (halves)
    const uint32_t kdst = (uint32_t)(kkey * 80 + kfc * 2);
    const uint32_t vdst = 5120u + (uint32_t)(vf * 144 + vkc * 2);
    __half* Pw = (__half*)(smraw + 29184 + w * 2304);   // [16][72]

    float o[4][4] = {};
    float m0r = -1e30f, m1r = -1e30f;
    float l0 = 0.f, l1 = 0.f;

    #pragma unroll
    for (int p = 0; p < 2; p++) {
        const uint32_t bo = smbase + p * BUFSTRIDE;
        const int jn = p * KT;
        cpa16(bo + kdst, kg + (size_t)(jn + kkey) * DH + kfc);
        cpa16(bo + vdst, vg + (size_t)vf * NTOK + jn + vkc);
        CPA_COMMIT();
    }

    int cur = 0, wb = 2;
    for (int tIdx = 0; tIdx < NTILES; tIdx++) {
        __syncthreads();
        if (tIdx + 2 < NTILES) {
            const uint32_t bo = smbase + wb * BUFSTRIDE;
            const int jn = (tIdx + 2) * KT;
            cpa16(bo + kdst, kg + (size_t)(jn + kkey) * DH + kfc);
            cpa16(bo + vdst, vg + (size_t)vf * NTOK + jn + vkc);
            CPA_COMMIT();
            asm volatile("cp.async.wait_group 2;");
        } else if (tIdx + 1 < NTILES) {
            asm volatile("cp.async.wait_group 1;");
        } else {
            asm volatile("cp.async.wait_group 0;");
        }

        const __half (*Ks)[40] = (const __half(*)[40])(smraw + cur * BUFSTRIDE);
        const __half (*Vs)[72] = (const __half(*)[72])(smraw + cur * BUFSTRIDE + 5120);
        wb = cur;
        cur = (cur == 2) ? 0 : cur + 1;

        // ---- S = Q K^T : 16q x 64key per warp, 16 HMMA ----
        float sc[8][4];
        #pragma unroll
        for (int nt = 0; nt < 8; nt++) {
            sc[nt][0] = sc[nt][1] = sc[nt][2] = sc[nt][3] = 0.f;
            #pragma unroll
            for (int ks = 0; ks < 2; ks++) {
                uint32_t b0 = *(const uint32_t*)&Ks[8 * nt + grp][16 * ks + 2 * tg];
                uint32_t b1 = *(const uint32_t*)&Ks[8 * nt + grp][16 * ks + 2 * tg + 8];
                mma_f16(sc[nt], qa[ks], b0, b1);
            }
        }

        // ---- online softmax (exp2 domain; Q pre-scaled) ----
        float mt0 = -1e30f, mt1 = -1e30f;
        #pragma unroll
        for (int nt = 0; nt < 8; nt++) {
            mt0 = fmaxf(mt0, fmaxf(sc[nt][0], sc[nt][1]));
            mt1 = fmaxf(mt1, fmaxf(sc[nt][2], sc[nt][3]));
        }
        mt0 = fmaxf(mt0, __shfl_xor_sync(0xffffffffu, mt0, 1));
        mt0 = fmaxf(mt0, __shfl_xor_sync(0xffffffffu, mt0, 2));
        mt1 = fmaxf(mt1, __shfl_xor_sync(0xffffffffu, mt1, 1));
        mt1 = fmaxf(mt1, __shfl_xor_sync(0xffffffffu, mt1, 2));
        float mn0 = fmaxf(m0r, mt0), mn1 = fmaxf(m1r, mt1);
        float c0 = ex2(m0r - mn0), c1 = ex2(m1r - mn1);
        m0r = mn0; m1r = mn1;
        l0 *= c0; l1 *= c1;
        #pragma unroll
        for (int nf = 0; nf < 4; nf++) {
            o[nf][0] *= c0; o[nf][1] *= c0;
            o[nf][2] *= c1; o[nf][3] *= c1;
        }
        float rs0 = 0.f, rs1 = 0.f;
        #pragma unroll
        for (int nt = 0; nt < 8; nt++) {
            float p0 = ex2(sc[nt][0] - mn0);
            float p1 = ex2(sc[nt][1] - mn0);
            float p2 = ex2(sc[nt][2] - mn1);
            float p3 = ex2(sc[nt][3] - mn1);
            rs0 += p0 + p1; rs1 += p2 + p3;
            *(__half2*)(Pw + (grp    ) * 72 + 8 * nt + 2 * tg) = __floats2half2_rn(p0, p1);
            *(__half2*)(Pw + (grp + 8) * 72 + 8 * nt + 2 * tg) = __floats2half2_rn(p2, p3);
        }
        rs0 += __shfl_xor_sync(0xffffffffu, rs0, 1);
        rs0 += __shfl_xor_sync(0xffffffffu, rs0, 2);
        rs1 += __shfl_xor_sync(0xffffffffu, rs1, 1);
        rs1 += __shfl_xor_sync(0xffffffffu, rs1, 2);
        l0 += rs0; l1 += rs1;
        __syncwarp();

        // ---- O += P V : 4 k-steps x 4 nf = 16 HMMA ----
        #pragma unroll
        for (int ks2 = 0; ks2 < 4; ks2++) {
            uint32_t pa[4];
            pa[0] = *(const uint32_t*)(Pw + (grp    ) * 72 + 16 * ks2 + 2 * tg);
            pa[1] = *(const uint32_t*)(Pw + (grp + 8) * 72 + 16 * ks2 + 2 * tg);
            pa[2] = *(const uint32_t*)(Pw + (grp    ) * 72 + 16 * ks2 + 2 * tg + 8);
            pa[3] = *(const uint32_t*)(Pw + (grp + 8) * 72 + 16 * ks2 + 2 * tg + 8);
            #pragma unroll
            for (int nf = 0; nf < 4; nf++) {
                uint32_t b0 = *(const uint32_t*)&Vs[8 * nf + grp][16 * ks2 + 2 * tg];
                uint32_t b1 = *(const uint32_t*)&Vs[8 * nf + grp][16 * ks2 + 2 * tg + 8];
                mma_f16(o[nf], pa, b0, b1);
            }
        }
    }
    __syncthreads();   // buffers free; Ofs aliases them

    // ---- epilogue: normalize, stage [f][tok], coalesced fp32 write ----
    float inv0 = 1.0f / l0, inv1 = 1.0f / l1;
    float* Ofs = (float*)smraw;   // [32][132]
    #pragma unroll
    for (int nf = 0; nf < 4; nf++) {
        int f0 = 8 * nf + 2 * tg;
        Ofs[(f0    ) * 132 + w * 16 + grp    ] = rtf(o[nf][0] * inv0);
        Ofs[(f0 + 1) * 132 + w * 16 + grp    ] = rtf(o[nf][1] * inv0);
        Ofs[(f0    ) * 132 + w * 16 + grp + 8] = rtf(o[nf][2] * inv1);
        Ofs[(f0 + 1) * 132 + w * 16 + grp + 8] = rtf(o[nf][3] * inv1);
    }
    __syncthreads();
    float* ob = g_att + ((size_t)b * HID + h * DH) * NTOK;
    #pragma unroll
    for (int i = 0; i < 4; i++) {
        int idx4 = tid + 256 * i;            // 1024 float4
        int f  = idx4 >> 5;
        int tc = (idx4 & 31) * 4;
        float4 v = *(const float4*)&Ofs[f * 132 + tc];
        *(float4*)(ob + (size_t)f * NTOK + n0 + tc) = v;
    }
}

// ================= launch =================
extern "C" void kernel_launch(void* const* d_in, const int* in_sizes, int n_in,
                              void* d_out, int out_size)
{
    const float* x    = (const float*)d_in[0];
    const float* gw   = (const float*)d_in[1];
    const float* gb   = (const float*)d_in[2];
    const float* wqkv = (const float*)d_in[3];
    const float* wout = (const float*)d_in[4];
    const float* bout = (const float*)d_in[5];
    float* out = (float*)d_out;

    float* att = nullptr; cudaGetSymbolAddress((void**)&att, g_att);
    float* xn  = nullptr; cudaGetSymbolAddress((void**)&xn,  g_xn);

    cudaFuncSetAttribute(k_attn, cudaFuncAttributeMaxDynamicSharedMemorySize, SMA_BYTES);

    k_gnstats<<<NB * 32, 256>>>(x, gw, gb);
    k_gemm<NQKV, NC, 1><<<dim3(64, 3, NB), 256>>>(wqkv, xn, nullptr, nullptr);
    k_attn<<<dim3(NTOK / QT, NHEAD, NB), 256, SMA_BYTES>>>();
    k_gemm<NC, HID, 0><<<dim3(64, 2, NB), 256>>>(wout, att, out, bout);
}

// round 8
// speedup vs baseline: 1.6895x; 1.0949x over previous
#include <cuda_runtime.h>
#include <cuda_fp16.h>
#include <math.h>
#include <stdint.h>

#define NB    4
#define NC    256
#define NTOK  4096
#define NHEAD 4
#define DH    32
#define HID   128
#define NQKV  384
#define CPG   8

// Q pre-scale: DH^-0.5 * log2(e)
#define QSCL 0.2550662672f

// -------- scratch --------
__device__ __half g_q[(size_t)NB * NHEAD * NTOK * DH];   // [b][h][tok][f] token-major, pre-scaled
__device__ __half g_k[(size_t)NB * NHEAD * NTOK * DH];   // [b][h][tok][f] token-major
__device__ __half g_v[(size_t)NB * HID * NTOK];          // [b][f][tok]   f-major
__device__ float  g_att[(size_t)NB * HID * NTOK];        // fp32 f-major
__device__ float  g_xn [(size_t)NB * NC * NTOK];         // normalized x, rna-tf32

// ---------- helpers ----------
__device__ __forceinline__ uint32_t f2tf(float f) {
    uint32_t u; asm("cvt.rna.tf32.f32 %0, %1;" : "=r"(u) : "f"(f)); return u;
}
__device__ __forceinline__ float rtf(float f) { return __uint_as_float(f2tf(f)); }
__device__ __forceinline__ float ex2(float x) {
    float y; asm("ex2.approx.ftz.f32 %0, %1;" : "=f"(y) : "f"(x)); return y;
}
__device__ __forceinline__ void mma_tf32(float c[4], const uint32_t a[4], uint32_t b0, uint32_t b1) {
    asm volatile("mma.sync.aligned.m16n8k8.row.col.f32.tf32.tf32.f32 "
                 "{%0,%1,%2,%3}, {%4,%5,%6,%7}, {%8,%9}, {%0,%1,%2,%3};"
                 : "+f"(c[0]), "+f"(c[1]), "+f"(c[2]), "+f"(c[3])
                 : "r"(a[0]), "r"(a[1]), "r"(a[2]), "r"(a[3]), "r"(b0), "r"(b1));
}
__device__ __forceinline__ void mma_f16(float c[4], const uint32_t a[4], uint32_t b0, uint32_t b1) {
    asm volatile("mma.sync.aligned.m16n8k16.row.col.f32.f16.f16.f32 "
                 "{%0,%1,%2,%3}, {%4,%5,%6,%7}, {%8,%9}, {%0,%1,%2,%3};"
                 : "+f"(c[0]), "+f"(c[1]), "+f"(c[2]), "+f"(c[3])
                 : "r"(a[0]), "r"(a[1]), "r"(a[2]), "r"(a[3]), "r"(b0), "r"(b1));
}
__device__ __forceinline__ void cpa16(uint32_t dst, const void* src) {
    asm volatile("cp.async.ca.shared.global [%0], [%1], 16;" :: "r"(dst), "l"(src));
}
#define CPA_COMMIT() asm volatile("cp.async.commit_group;")

// ================= GroupNorm: stats + write normalized x (rna-tf32) =================
__global__ void __launch_bounds__(256) k_gnstats(const float* __restrict__ x,
                                                 const float* __restrict__ gw,
                                                 const float* __restrict__ gb)
{
    const int b = blockIdx.x >> 5;
    const int g = blockIdx.x & 31;
    const size_t base = ((size_t)(b * NC + g * CPG)) * NTOK;
    const float4* p4 = (const float4*)(x + base);
    float4* o4 = (float4*)(g_xn + base);
    float s = 0.f, s2 = 0.f;
    for (int i = threadIdx.x; i < 8192; i += 256) {
        float4 v = p4[i];
        s  += (v.x + v.y) + (v.z + v.w);
        s2 += v.x * v.x + v.y * v.y + v.z * v.z + v.w * v.w;
    }
    #pragma unroll
    for (int off = 16; off; off >>= 1) {
        s  += __shfl_xor_sync(0xffffffffu, s,  off);
        s2 += __shfl_xor_sync(0xffffffffu, s2, off);
    }
    __shared__ float ws[8], ws2[8];
    __shared__ float al8[CPG], be8[CPG];
    const int w = threadIdx.x >> 5;
    if ((threadIdx.x & 31) == 0) { ws[w] = s; ws2[w] = s2; }
    __syncthreads();
    if (threadIdx.x < CPG) {
        float t = 0.f, t2 = 0.f;
        #pragma unroll
        for (int i = 0; i < 8; i++) { t += ws[i]; t2 += ws2[i]; }
        float mean = t * (1.f / 32768.f);
        float var  = t2 * (1.f / 32768.f) - mean * mean;
        float sr = rsqrtf(var + 1e-5f);
        int c = g * CPG + threadIdx.x;
        float a = gw[c] * sr;
        al8[threadIdx.x] = a;
        be8[threadIdx.x] = gb[c] - mean * a;
    }
    __syncthreads();
    for (int i = threadIdx.x; i < 8192; i += 256) {
        int cl = i >> 10;
        float a = al8[cl], bb = be8[cl];
        float4 v = p4[i];
        o4[i] = make_float4(rtf(fmaf(v.x, a, bb)), rtf(fmaf(v.y, a, bb)),
                            rtf(fmaf(v.z, a, bb)), rtf(fmaf(v.w, a, bb)));
    }
}

// ================= pipelined tf32 GEMM (unchanged from R7) =================
template<int MTOT, int KTOT, int OMODE>
__global__ void __launch_bounds__(256) k_gemm(const float* __restrict__ A,
                                              const float* __restrict__ Bg,
                                              float* __restrict__ Cg,
                                              const float* __restrict__ bias)
{
    constexpr int NK = KTOT / 32;
    const int b  = blockIdx.z;
    const int m0 = blockIdx.y * 128;
    const int n0 = blockIdx.x * 64;
    __shared__ float As[128][36];
    __shared__ float Xs[2][32][72];
    const float* Bb = Bg + (size_t)b * KTOT * NTOK;
    const int tid = threadIdx.x, w = tid >> 5, lane = tid & 31;
    const int g = lane >> 2, t = lane & 3;
    const int wm = (w >> 1) * 32, wn = (w & 1) * 32;
    const uint32_t xsbase = (uint32_t)__cvta_generic_to_shared(&Xs[0][0][0]);
    const int kcA = tid >> 4, ncA = (tid & 15) << 2;
    const int kcB = kcA + 16;

    float4 ar[2][4];
    float acc[2][4][4] = {};

    cpa16(xsbase + kcA * 288 + ncA * 4, Bb + (size_t)kcA * NTOK + n0 + ncA);
    cpa16(xsbase + kcB * 288 + ncA * 4, Bb + (size_t)kcB * NTOK + n0 + ncA);
    CPA_COMMIT();
    #pragma unroll
    for (int i = 0; i < 4; i++) {
        int id = tid + 256 * i, m = id >> 3, c = (id & 7) << 2;
        ar[0][i] = *(const float4*)(A + (size_t)(m0 + m) * KTOT + c);
    }

    #pragma unroll
    for (int k = 0; k < NK; k++) {
        __syncthreads();
        #pragma unroll
        for (int i = 0; i < 4; i++) {
            int id = tid + 256 * i, m = id >> 3, c = (id & 7) << 2;
            float4 v = ar[k & 1][i];
            As[m][c] = rtf(v.x); As[m][c + 1] = rtf(v.y);
            As[m][c + 2] = rtf(v.z); As[m][c + 3] = rtf(v.w);
        }
        if (k + 1 < NK) {
            uint32_t bo = xsbase + ((k + 1) & 1) * 9216;
            cpa16(bo + kcA * 288 + ncA * 4, Bb + (size_t)((k + 1) * 32 + kcA) * NTOK + n0 + ncA);
            cpa16(bo + kcB * 288 + ncA * 4, Bb + (size_t)((k + 1) * 32 + kcB) * NTOK + n0 + ncA);
            CPA_COMMIT();
            #pragma unroll
            for (int i = 0; i < 4; i++) {
                int id = tid + 256 * i, m = id >> 3, c = (id & 7) << 2;
                ar[(k + 1) & 1][i] = *(const float4*)(A + (size_t)(m0 + m) * KTOT + (k + 1) * 32 + c);
            }
            asm volatile("cp.async.wait_group 1;");
        } else {
            asm volatile("cp.async.wait_group 0;");
        }
        __syncthreads();
        const float (*X)[72] = Xs[k & 1];
        #pragma unroll
        for (int ks = 0; ks < 4; ks++) {
            uint32_t a[2][4];
            #pragma unroll
            for (int mf = 0; mf < 2; mf++) {
                int r = wm + 16 * mf + g;
                a[mf][0] = __float_as_uint(As[r    ][8 * ks + t]);
                a[mf][1] = __float_as_uint(As[r + 8][8 * ks + t]);
                a[mf][2] = __float_as_uint(As[r    ][8 * ks + t + 4]);
                a[mf][3] = __float_as_uint(As[r + 8][8 * ks + t + 4]);
            }
            #pragma unroll
            for (int nf = 0; nf < 4; nf++) {
                uint32_t b0 = __float_as_uint(X[8 * ks + t    ][wn + 8 * nf + g]);
                uint32_t b1 = __float_as_uint(X[8 * ks + t + 4][wn + 8 * nf + g]);
                mma_tf32(acc[0][nf], a[0], b0, b1);
                mma_tf32(acc[1][nf], a[1], b0, b1);
            }
        }
    }

    if (OMODE == 0) {
        float* Cb = Cg + (size_t)b * MTOT * NTOK;
        #pragma unroll
        for (int mf = 0; mf < 2; mf++) {
            int row = m0 + wm + 16 * mf + g;
            float bv0 = bias[row], bv8 = bias[row + 8];
            #pragma unroll
            for (int nf = 0; nf < 4; nf++) {
                int col = n0 + wn + 8 * nf + 2 * t;
                *(float2*)(Cb + (size_t)row * NTOK + col) =
                    make_float2(acc[mf][nf][0] + bv0, acc[mf][nf][1] + bv0);
                *(float2*)(Cb + (size_t)(row + 8) * NTOK + col) =
                    make_float2(acc[mf][nf][2] + bv8, acc[mf][nf][3] + bv8);
            }
        }
    } else {
        const int sel = blockIdx.y;          // 0=Q 1=K 2=V
        #pragma unroll
        for (int mf = 0; mf < 2; mf++) {
            int row = wm + 16 * mf + g;
            #pragma unroll
            for (int nf = 0; nf < 4; nf++) {
                int col = n0 + wn + 8 * nf + 2 * t;
                float v0 = acc[mf][nf][0], v1 = acc[mf][nf][1];
                float v2 = acc[mf][nf][2], v3 = acc[mf][nf][3];
                if (sel == 0) { v0 *= QSCL; v1 *= QSCL; v2 *= QSCL; v3 *= QSCL; }
                if (sel < 2) {
                    __half* base = (sel == 0 ? g_q : g_k)
                        + ((size_t)(b * NHEAD + (row >> 5)) * NTOK + col) * DH + (row & 31);
                    base[0]      = __float2half_rn(v0);
                    base[DH]     = __float2half_rn(v1);
                    base[8]      = __float2half_rn(v2);
                    base[DH + 8] = __float2half_rn(v3);
                } else {
                    *(__half2*)&g_v[((size_t)(b * HID + row)) * NTOK + col] =
                        __floats2half2_rn(v0, v1);
                    *(__half2*)&g_v[((size_t)(b * HID + row + 8)) * NTOK + col] =
                        __floats2half2_rn(v2, v3);
                }
            }
        }
    }
}

// ================= Flash attention: fixed-offset softmax, l via ones-row mma =================
// dyn SMEM (bytes):
//  buf(i) @ i*10880, i=0..2 : K [64 key][40 f] half (5120) + V [40 f][72 key] half (5760)
//     V rows 0..31 = data (re-staged per tile); row 32 = 1.0 ones; rows 33..39 = 0 (persistent)
//  P @ 32640 : 8 warps x [16][72] half (2304 each) = 18432   -> total 51072
//  Qs @ 0 : [128 tok][40 f] half = 10240 (prologue alias)
//  Ofs @ 0 : [32 f][132 tok] float = 16896 (epilogue alias)
#define QT 128
#define KT 64
#define NTILES (NTOK / KT)
#define BUFSTRIDE 10880u
#define SMA_BYTES 51072
__global__ void __launch_bounds__(256, 3) k_attn()
{
    extern __shared__ __align__(16) char smraw[];
    __half (*Qs)[40] = (__half(*)[40])smraw;
    const uint32_t smbase = (uint32_t)__cvta_generic_to_shared(smraw);

    const int b  = blockIdx.z, h = blockIdx.y;
    const int n0 = blockIdx.x * QT;
    const int tid  = threadIdx.x;
    const int w    = tid >> 5;
    const int lane = tid & 31;
    const int grp  = lane >> 2;
    const int tg   = lane & 3;

    const __half* qg = g_q + (size_t)(b * NHEAD + h) * NTOK * DH;
    const __half* kg = g_k + (size_t)(b * NHEAD + h) * NTOK * DH;
    const __half* vg = g_v + (size_t)(b * HID + h * DH) * NTOK;

    // ---- prologue: stage Q tile [128 tok][32 f] ----
    #pragma unroll
    for (int i = 0; i < 2; i++) {
        int chunk = tid + 256 * i;
        int tok = chunk >> 2;
        int fc  = (chunk & 3) * 8;
        cpa16(smbase + (uint32_t)(tok * 80 + fc * 2), qg + (size_t)(n0 + tok) * DH + fc);
    }
    CPA_COMMIT();
    asm volatile("cp.async.wait_group 0;");
    __syncthreads();

    const int qrow = w * 16 + grp;
    uint32_t qa[2][4];
    #pragma unroll
    for (int ks = 0; ks < 2; ks++) {
        qa[ks][0] = *(const uint32_t*)&Qs[qrow    ][16 * ks + 2 * tg];
        qa[ks][1] = *(const uint32_t*)&Qs[qrow + 8][16 * ks + 2 * tg];
        qa[ks][2] = *(const uint32_t*)&Qs[qrow    ][16 * ks + 2 * tg + 8];
        qa[ks][3] = *(const uint32_t*)&Qs[qrow + 8][16 * ks + 2 * tg + 8];
    }
    __syncthreads();   // Q reads done before buffer init/staging overwrites alias

    // ---- init persistent V rows 32..39 of each buffer: row32=1.0, rows33..39=0 ----
    if (tid < 216) {
        int buf = tid / 72, idx = tid % 72;            // 72 x 16B per buffer region
        uint4 val = (idx < 9) ? make_uint4(0x3C003C00u, 0x3C003C00u, 0x3C003C00u, 0x3C003C00u)
                              : make_uint4(0u, 0u, 0u, 0u);
        *(uint4*)(smraw + buf * BUFSTRIDE + 5120 + 32 * 144 + (idx % 9) * 16 + (idx / 9) * 144) = val;
    }

    // staging coords
    const int kkey = tid >> 2;
    const int kfc  = (tid & 3) * 8;
    const int vf   = tid >> 3;
    const int vkc  = (tid & 7) * 8;
    const uint32_t kdst = (uint32_t)(kkey * 80 + kfc * 2);
    const uint32_t vdst = 5120u + (uint32_t)(vf * 144 + vkc * 2);
    __half* Pw = (__half*)(smraw + 32640 + w * 2304);   // [16][72]

    float o[4][4] = {};
    float lc[4] = {};   // l accumulator via ones-row mma (col 32 -> c[0]/c[2] of tg==0)

    #pragma unroll
    for (int p = 0; p < 2; p++) {
        const uint32_t bo = smbase + p * BUFSTRIDE;
        const int jn = p * KT;
        cpa16(bo + kdst, kg + (size_t)(jn + kkey) * DH + kfc);
        cpa16(bo + vdst, vg + (size_t)vf * NTOK + jn + vkc);
        CPA_COMMIT();
    }

    int cur = 0, wb = 2;
    for (int tIdx = 0; tIdx < NTILES; tIdx++) {
        __syncthreads();
        if (tIdx + 2 < NTILES) {
            const uint32_t bo = smbase + wb * BUFSTRIDE;
            const int jn = (tIdx + 2) * KT;
            cpa16(bo + kdst, kg + (size_t)(jn + kkey) * DH + kfc);
            cpa16(bo + vdst, vg + (size_t)vf * NTOK + jn + vkc);
            CPA_COMMIT();
            asm volatile("cp.async.wait_group 2;");
        } else if (tIdx + 1 < NTILES) {
            asm volatile("cp.async.wait_group 1;");
        } else {
            asm volatile("cp.async.wait_group 0;");
        }

        const __half (*Ks)[40] = (const __half(*)[40])(smraw + cur * BUFSTRIDE);
        const __half (*Vs)[72] = (const __half(*)[72])(smraw + cur * BUFSTRIDE + 5120);
        wb = cur;
        cur = (cur == 2) ? 0 : cur + 1;

        // ---- S = Q K^T - 8 (offset folded into accumulator init) ----
        float sc[8][4];
        #pragma unroll
        for (int nt = 0; nt < 8; nt++) {
            sc[nt][0] = sc[nt][1] = sc[nt][2] = sc[nt][3] = -8.f;
            #pragma unroll
            for (int ks = 0; ks < 2; ks++) {
                uint32_t b0 = *(const uint32_t*)&Ks[8 * nt + grp][16 * ks + 2 * tg];
                uint32_t b1 = *(const uint32_t*)&Ks[8 * nt + grp][16 * ks + 2 * tg + 8];
                mma_f16(sc[nt], qa[ks], b0, b1);
            }
        }

        // ---- p = exp2(s - 8); store fp16 P (no max, no rescale, no shuffles) ----
        #pragma unroll
        for (int nt = 0; nt < 8; nt++) {
            float p0 = ex2(sc[nt][0]);
            float p1 = ex2(sc[nt][1]);
            float p2 = ex2(sc[nt][2]);
            float p3 = ex2(sc[nt][3]);
            *(__half2*)(Pw + (grp    ) * 72 + 8 * nt + 2 * tg) = __floats2half2_rn(p0, p1);
            *(__half2*)(Pw + (grp + 8) * 72 + 8 * nt + 2 * tg) = __floats2half2_rn(p2, p3);
        }
        __syncwarp();

        // ---- O += P V (nf 0..3) and l += P 1 (ones-row block) ----
        #pragma unroll
        for (int ks2 = 0; ks2 < 4; ks2++) {
            uint32_t pa[4];
            pa[0] = *(const uint32_t*)(Pw + (grp    ) * 72 + 16 * ks2 + 2 * tg);
            pa[1] = *(const uint32_t*)(Pw + (grp + 8) * 72 + 16 * ks2 + 2 * tg);
            pa[2] = *(const uint32_t*)(Pw + (grp    ) * 72 + 16 * ks2 + 2 * tg + 8);
            pa[3] = *(const uint32_t*)(Pw + (grp + 8) * 72 + 16 * ks2 + 2 * tg + 8);
            #pragma unroll
            for (int nf = 0; nf < 4; nf++) {
                uint32_t b0 = *(const uint32_t*)&Vs[8 * nf + grp][16 * ks2 + 2 * tg];
                uint32_t b1 = *(const uint32_t*)&Vs[8 * nf + grp][16 * ks2 + 2 * tg + 8];
                mma_f16(o[nf], pa, b0, b1);
            }
            uint32_t c0 = *(const uint32_t*)&Vs[32 + grp][16 * ks2 + 2 * tg];
            uint32_t c1 = *(const uint32_t*)&Vs[32 + grp][16 * ks2 + 2 * tg + 8];
            mma_f16(lc, pa, c0, c1);
        }
    }
    __syncthreads();   // buffers free; Ofs aliases them

    // ---- l broadcast: col 32 lives in c[0]/c[2] of tg==0 thread of each group ----
    float l0 = __shfl_sync(0xffffffffu, lc[0], lane & ~3);
    float l1 = __shfl_sync(0xffffffffu, lc[2], lane & ~3);

    // ---- epilogue: normalize, stage [f][tok], coalesced fp32 write ----
    float inv0 = 1.0f / l0, inv1 = 1.0f / l1;
    float* Ofs = (float*)smraw;   // [32][132]
    #pragma unroll
    for (int nf = 0; nf < 4; nf++) {
        int f0 = 8 * nf + 2 * tg;
        Ofs[(f0    ) * 132 + w * 16 + grp    ] = rtf(o[nf][0] * inv0);
        Ofs[(f0 + 1) * 132 + w * 16 + grp    ] = rtf(o[nf][1] * inv0);
        Ofs[(f0    ) * 132 + w * 16 + grp + 8] = rtf(o[nf][2] * inv1);
        Ofs[(f0 + 1) * 132 + w * 16 + grp + 8] = rtf(o[nf][3] * inv1);
    }
    __syncthreads();
    float* ob = g_att + ((size_t)b * HID + h * DH) * NTOK;
    #pragma unroll
    for (int i = 0; i < 4; i++) {
        int idx4 = tid + 256 * i;
        int f  = idx4 >> 5;
        int tc = (idx4 & 31) * 4;
        float4 v = *(const float4*)&Ofs[f * 132 + tc];
        *(float4*)(ob + (size_t)f * NTOK + n0 + tc) = v;
    }
}

// ================= launch =================
extern "C" void kernel_launch(void* const* d_in, const int* in_sizes, int n_in,
                              void* d_out, int out_size)
{
    const float* x    = (const float*)d_in[0];
    const float* gw   = (const float*)d_in[1];
    const float* gb   = (const float*)d_in[2];
    const float* wqkv = (const float*)d_in[3];
    const float* wout = (const float*)d_in[4];
    const float* bout = (const float*)d_in[5];
    float* out = (float*)d_out;

    float* att = nullptr; cudaGetSymbolAddress((void**)&att, g_att);
    float* xn  = nullptr; cudaGetSymbolAddress((void**)&xn,  g_xn);

    cudaFuncSetAttribute(k_attn, cudaFuncAttributeMaxDynamicSharedMemorySize, SMA_BYTES);

    k_gnstats<<<NB * 32, 256>>>(x, gw, gb);
    k_gemm<NQKV, NC, 1><<<dim3(64, 3, NB), 256>>>(wqkv, xn, nullptr, nullptr);
    k_attn<<<dim3(NTOK / QT, NHEAD, NB), 256, SMA_BYTES>>>();
    k_gemm<NC, HID, 0><<<dim3(64, 2, NB), 256>>>(wout, att, out, bout);
}

// round 9
// speedup vs baseline: 1.7082x; 1.0111x over previous
#include <cuda_runtime.h>
#include <cuda_fp16.h>
#include <math.h>
#include <stdint.h>

#define NB    4
#define NC    256
#define NTOK  4096
#define NHEAD 4
#define DH    32
#define HID   128
#define NQKV  384
#define CPG   8

// Q pre-scale: DH^-0.5 * log2(e)
#define QSCL 0.2550662672f

// -------- scratch --------
__device__ __half g_q[(size_t)NB * NHEAD * NTOK * DH];   // [b][h][tok][f] token-major, pre-scaled
__device__ __half g_k[(size_t)NB * NHEAD * NTOK * DH];   // [b][h][tok][f] token-major
__device__ __half g_v[(size_t)NB * HID * NTOK];          // [b][f][tok]   f-major
__device__ float  g_att[(size_t)NB * HID * NTOK];        // fp32 f-major
__device__ float  g_xn [(size_t)NB * NC * NTOK];         // normalized x, rna-tf32

// ---------- helpers ----------
__device__ __forceinline__ uint32_t f2tf(float f) {
    uint32_t u; asm("cvt.rna.tf32.f32 %0, %1;" : "=r"(u) : "f"(f)); return u;
}
__device__ __forceinline__ float rtf(float f) { return __uint_as_float(f2tf(f)); }
__device__ __forceinline__ float ex2(float x) {
    float y; asm("ex2.approx.ftz.f32 %0, %1;" : "=f"(y) : "f"(x)); return y;
}
__device__ __forceinline__ void mma_tf32(float c[4], const uint32_t a[4], uint32_t b0, uint32_t b1) {
    asm volatile("mma.sync.aligned.m16n8k8.row.col.f32.tf32.tf32.f32 "
                 "{%0,%1,%2,%3}, {%4,%5,%6,%7}, {%8,%9}, {%0,%1,%2,%3};"
                 : "+f"(c[0]), "+f"(c[1]), "+f"(c[2]), "+f"(c[3])
                 : "r"(a[0]), "r"(a[1]), "r"(a[2]), "r"(a[3]), "r"(b0), "r"(b1));
}
__device__ __forceinline__ void mma_f16(float c[4], const uint32_t a[4], uint32_t b0, uint32_t b1) {
    asm volatile("mma.sync.aligned.m16n8k16.row.col.f32.f16.f16.f32 "
                 "{%0,%1,%2,%3}, {%4,%5,%6,%7}, {%8,%9}, {%0,%1,%2,%3};"
                 : "+f"(c[0]), "+f"(c[1]), "+f"(c[2]), "+f"(c[3])
                 : "r"(a[0]), "r"(a[1]), "r"(a[2]), "r"(a[3]), "r"(b0), "r"(b1));
}
__device__ __forceinline__ void cpa16(uint32_t dst, const void* src) {
    asm volatile("cp.async.ca.shared.global [%0], [%1], 16;" :: "r"(dst), "l"(src));
}
#define CPA_COMMIT() asm volatile("cp.async.commit_group;")

// ================= GroupNorm: stats + write normalized x (rna-tf32) =================
__global__ void __launch_bounds__(256) k_gnstats(const float* __restrict__ x,
                                                 const float* __restrict__ gw,
                                                 const float* __restrict__ gb)
{
    const int b = blockIdx.x >> 5;
    const int g = blockIdx.x & 31;
    const size_t base = ((size_t)(b * NC + g * CPG)) * NTOK;
    const float4* p4 = (const float4*)(x + base);
    float4* o4 = (float4*)(g_xn + base);
    float s = 0.f, s2 = 0.f;
    for (int i = threadIdx.x; i < 8192; i += 256) {
        float4 v = p4[i];
        s  += (v.x + v.y) + (v.z + v.w);
        s2 += v.x * v.x + v.y * v.y + v.z * v.z + v.w * v.w;
    }
    #pragma unroll
    for (int off = 16; off; off >>= 1) {
        s  += __shfl_xor_sync(0xffffffffu, s,  off);
        s2 += __shfl_xor_sync(0xffffffffu, s2, off);
    }
    __shared__ float ws[8], ws2[8];
    __shared__ float al8[CPG], be8[CPG];
    const int w = threadIdx.x >> 5;
    if ((threadIdx.x & 31) == 0) { ws[w] = s; ws2[w] = s2; }
    __syncthreads();
    if (threadIdx.x < CPG) {
        float t = 0.f, t2 = 0.f;
        #pragma unroll
        for (int i = 0; i < 8; i++) { t += ws[i]; t2 += ws2[i]; }
        float mean = t * (1.f / 32768.f);
        float var  = t2 * (1.f / 32768.f) - mean * mean;
        float sr = rsqrtf(var + 1e-5f);
        int c = g * CPG + threadIdx.x;
        float a = gw[c] * sr;
        al8[threadIdx.x] = a;
        be8[threadIdx.x] = gb[c] - mean * a;
    }
    __syncthreads();
    for (int i = threadIdx.x; i < 8192; i += 256) {
        int cl = i >> 10;
        float a = al8[cl], bb = be8[cl];
        float4 v = p4[i];
        o4[i] = make_float4(rtf(fmaf(v.x, a, bb)), rtf(fmaf(v.y, a, bb)),
                            rtf(fmaf(v.z, a, bb)), rtf(fmaf(v.w, a, bb)));
    }
}

// ================= pipelined tf32 GEMM =================
// OMODE 0: fp32 out + bias. OMODE 1: QKV fp16 out; blockIdx.y: 0=Q 1=K (token-major,
// SMEM-staged coalesced stores) 2=V (f-major half2 stores).
template<int MTOT, int KTOT, int OMODE>
__global__ void __launch_bounds__(256) k_gemm(const float* __restrict__ A,
                                              const float* __restrict__ Bg,
                                              float* __restrict__ Cg,
                                              const float* __restrict__ bias)
{
    constexpr int NK = KTOT / 32;
    const int b  = blockIdx.z;
    const int m0 = blockIdx.y * 128;
    const int n0 = blockIdx.x * 64;
    __shared__ float As[128][36];
    __shared__ float Xs[2][32][72];
    const float* Bb = Bg + (size_t)b * KTOT * NTOK;
    const int tid = threadIdx.x, w = tid >> 5, lane = tid & 31;
    const int g = lane >> 2, t = lane & 3;
    const int wm = (w >> 1) * 32, wn = (w & 1) * 32;
    const uint32_t xsbase = (uint32_t)__cvta_generic_to_shared(&Xs[0][0][0]);
    const int kcA = tid >> 4, ncA = (tid & 15) << 2;
    const int kcB = kcA + 16;

    float4 ar[2][4];
    float acc[2][4][4] = {};

    cpa16(xsbase + kcA * 288 + ncA * 4, Bb + (size_t)kcA * NTOK + n0 + ncA);
    cpa16(xsbase + kcB * 288 + ncA * 4, Bb + (size_t)kcB * NTOK + n0 + ncA);
    CPA_COMMIT();
    #pragma unroll
    for (int i = 0; i < 4; i++) {
        int id = tid + 256 * i, m = id >> 3, c = (id & 7) << 2;
        ar[0][i] = *(const float4*)(A + (size_t)(m0 + m) * KTOT + c);
    }

    #pragma unroll
    for (int k = 0; k < NK; k++) {
        __syncthreads();
        #pragma unroll
        for (int i = 0; i < 4; i++) {
            int id = tid + 256 * i, m = id >> 3, c = (id & 7) << 2;
            float4 v = ar[k & 1][i];
            As[m][c] = rtf(v.x); As[m][c + 1] = rtf(v.y);
            As[m][c + 2] = rtf(v.z); As[m][c + 3] = rtf(v.w);
        }
        if (k + 1 < NK) {
            uint32_t bo = xsbase + ((k + 1) & 1) * 9216;
            cpa16(bo + kcA * 288 + ncA * 4, Bb + (size_t)((k + 1) * 32 + kcA) * NTOK + n0 + ncA);
            cpa16(bo + kcB * 288 + ncA * 4, Bb + (size_t)((k + 1) * 32 + kcB) * NTOK + n0 + ncA);
            CPA_COMMIT();
            #pragma unroll
            for (int i = 0; i < 4; i++) {
                int id = tid + 256 * i, m = id >> 3, c = (id & 7) << 2;
                ar[(k + 1) & 1][i] = *(const float4*)(A + (size_t)(m0 + m) * KTOT + (k + 1) * 32 + c);
            }
            asm volatile("cp.async.wait_group 1;");
        } else {
            asm volatile("cp.async.wait_group 0;");
        }
        __syncthreads();
        const float (*X)[72] = Xs[k & 1];
        #pragma unroll
        for (int ks = 0; ks < 4; ks++) {
            uint32_t a[2][4];
            #pragma unroll
            for (int mf = 0; mf < 2; mf++) {
                int r = wm + 16 * mf + g;
                a[mf][0] = __float_as_uint(As[r    ][8 * ks + t]);
                a[mf][1] = __float_as_uint(As[r + 8][8 * ks + t]);
                a[mf][2] = __float_as_uint(As[r    ][8 * ks + t + 4]);
                a[mf][3] = __float_as_uint(As[r + 8][8 * ks + t + 4]);
            }
            #pragma unroll
            for (int nf = 0; nf < 4; nf++) {
                uint32_t b0 = __float_as_uint(X[8 * ks + t    ][wn + 8 * nf + g]);
                uint32_t b1 = __float_as_uint(X[8 * ks + t + 4][wn + 8 * nf + g]);
                mma_tf32(acc[0][nf], a[0], b0, b1);
                mma_tf32(acc[1][nf], a[1], b0, b1);
            }
        }
    }

    if (OMODE == 0) {
        float* Cb = Cg + (size_t)b * MTOT * NTOK;
        #pragma unroll
        for (int mf = 0; mf < 2; mf++) {
            int row = m0 + wm + 16 * mf + g;
            float bv0 = bias[row], bv8 = bias[row + 8];
            #pragma unroll
            for (int nf = 0; nf < 4; nf++) {
                int col = n0 + wn + 8 * nf + 2 * t;
                *(float2*)(Cb + (size_t)row * NTOK + col) =
                    make_float2(acc[mf][nf][0] + bv0, acc[mf][nf][1] + bv0);
                *(float2*)(Cb + (size_t)(row + 8) * NTOK + col) =
                    make_float2(acc[mf][nf][2] + bv8, acc[mf][nf][3] + bv8);
            }
        }
    } else {
        const int sel = blockIdx.y;          // 0=Q 1=K 2=V
        if (sel == 2) {
            #pragma unroll
            for (int mf = 0; mf < 2; mf++) {
                int row = wm + 16 * mf + g;
                #pragma unroll
                for (int nf = 0; nf < 4; nf++) {
                    int col = n0 + wn + 8 * nf + 2 * t;
                    *(__half2*)&g_v[((size_t)(b * HID + row)) * NTOK + col] =
                        __floats2half2_rn(acc[mf][nf][0], acc[mf][nf][1]);
                    *(__half2*)&g_v[((size_t)(b * HID + row + 8)) * NTOK + col] =
                        __floats2half2_rn(acc[mf][nf][2], acc[mf][nf][3]);
                }
            }
        } else {
            // SMEM-staged coalesced store: Sm[tok(64)][m(128)+8pad] halves (aliases As)
            __half* Sm = (__half*)&As[0][0];   // 64*136*2 = 17408 B <= 18432 B
            const float scl = (sel == 0) ? QSCL : 1.0f;
            __syncthreads();                    // last-iter As/Xs reads done
            #pragma unroll
            for (int mf = 0; mf < 2; mf++) {
                int r = wm + 16 * mf + g;
                #pragma unroll
                for (int nf = 0; nf < 4; nf++) {
                    int c = wn + 8 * nf + 2 * t;
                    Sm[(c    ) * 136 + r    ] = __float2half_rn(acc[mf][nf][0] * scl);
                    Sm[(c + 1) * 136 + r    ] = __float2half_rn(acc[mf][nf][1] * scl);
                    Sm[(c    ) * 136 + r + 8] = __float2half_rn(acc[mf][nf][2] * scl);
                    Sm[(c + 1) * 136 + r + 8] = __float2half_rn(acc[mf][nf][3] * scl);
                }
            }
            __syncthreads();
            __half* dstb = (sel == 0) ? g_q : g_k;
            #pragma unroll
            for (int i = 0; i < 4; i++) {
                int id = tid + 256 * i;        // 1024 chunks of 8 halves
                int tok = id >> 4;
                int mc  = id & 15;             // m-chunk: m = 8*mc
                int hh  = mc >> 2;             // head
                int f0  = (mc & 3) * 8;
                uint4 v = *(const uint4*)&Sm[tok * 136 + mc * 8];
                *(uint4*)(dstb + ((size_t)(b * NHEAD + hh) * NTOK + n0 + tok) * DH + f0) = v;
            }
        }
    }
}

// ================= Flash attention: offset-0 softmax, deferred l reduction =================
// dyn SMEM (bytes):
//  buf(i) @ i*9728, i=0..2 : K [64 key][40 f] half (5120) + V [32 f][72 key] half (4608)
//  P @ 29184 : 8 warps x [16][72] half (2304 each) = 18432   -> total 47616
//  Qs @ 0 : [128 tok][40 f] half = 10240 (prologue alias)
//  Ofs @ 0 : [32 f][132 tok] float = 16896 (epilogue alias)
#define QT 128
#define KT 64
#define NTILES (NTOK / KT)
#define BUFSTRIDE 9728u
#define SMA_BYTES 47616
__global__ void __launch_bounds__(256, 3) k_attn()
{
    extern __shared__ __align__(16) char smraw[];
    __half (*Qs)[40] = (__half(*)[40])smraw;
    const uint32_t smbase = (uint32_t)__cvta_generic_to_shared(smraw);

    const int b  = blockIdx.z, h = blockIdx.y;
    const int n0 = blockIdx.x * QT;
    const int tid  = threadIdx.x;
    const int w    = tid >> 5;
    const int lane = tid & 31;
    const int grp  = lane >> 2;
    const int tg   = lane & 3;

    const __half* qg = g_q + (size_t)(b * NHEAD + h) * NTOK * DH;
    const __half* kg = g_k + (size_t)(b * NHEAD + h) * NTOK * DH;
    const __half* vg = g_v + (size_t)(b * HID + h * DH) * NTOK;

    // ---- prologue: stage Q tile [128 tok][32 f] ----
    #pragma unroll
    for (int i = 0; i < 2; i++) {
        int chunk = tid + 256 * i;
        int tok = chunk >> 2;
        int fc  = (chunk & 3) * 8;
        cpa16(smbase + (uint32_t)(tok * 80 + fc * 2), qg + (size_t)(n0 + tok) * DH + fc);
    }
    CPA_COMMIT();
    asm volatile("cp.async.wait_group 0;");
    __syncthreads();

    const int qrow = w * 16 + grp;
    uint32_t qa[2][4];
    #pragma unroll
    for (int ks = 0; ks < 2; ks++) {
        qa[ks][0] = *(const uint32_t*)&Qs[qrow    ][16 * ks + 2 * tg];
        qa[ks][1] = *(const uint32_t*)&Qs[qrow + 8][16 * ks + 2 * tg];
        qa[ks][2] = *(const uint32_t*)&Qs[qrow    ][16 * ks + 2 * tg + 8];
        qa[ks][3] = *(const uint32_t*)&Qs[qrow + 8][16 * ks + 2 * tg + 8];
    }
    __syncthreads();   // Q reads done before staging overwrites alias

    // staging coords
    const int kkey = tid >> 2;
    const int kfc  = (tid & 3) * 8;
    const int vf   = tid >> 3;
    const int vkc  = (tid & 7) * 8;
    const uint32_t kdst = (uint32_t)(kkey * 80 + kfc * 2);
    const uint32_t vdst = 5120u + (uint32_t)(vf * 144 + vkc * 2);
    __half* Pw = (__half*)(smraw + 29184 + w * 2304);   // [16][72]

    float o[4][4] = {};
    float l0p = 0.f, l1p = 0.f;   // per-thread partial row sums (reduced once at end)

    #pragma unroll
    for (int p = 0; p < 2; p++) {
        const uint32_t bo = smbase + p * BUFSTRIDE;
        const int jn = p * KT;
        cpa16(bo + kdst, kg + (size_t)(jn + kkey) * DH + kfc);
        cpa16(bo + vdst, vg + (size_t)vf * NTOK + jn + vkc);
        CPA_COMMIT();
    }

    int cur = 0, wb = 2;
    for (int tIdx = 0; tIdx < NTILES; tIdx++) {
        __syncthreads();
        if (tIdx + 2 < NTILES) {
            const uint32_t bo = smbase + wb * BUFSTRIDE;
            const int jn = (tIdx + 2) * KT;
            cpa16(bo + kdst, kg + (size_t)(jn + kkey) * DH + kfc);
            cpa16(bo + vdst, vg + (size_t)vf * NTOK + jn + vkc);
            CPA_COMMIT();
            asm volatile("cp.async.wait_group 2;");
        } else if (tIdx + 1 < NTILES) {
            asm volatile("cp.async.wait_group 1;");
        } else {
            asm volatile("cp.async.wait_group 0;");
        }

        const __half (*Ks)[40] = (const __half(*)[40])(smraw + cur * BUFSTRIDE);
        const __half (*Vs)[72] = (const __half(*)[72])(smraw + cur * BUFSTRIDE + 5120);
        wb = cur;
        cur = (cur == 2) ? 0 : cur + 1;

        // ---- S = Q K^T ----
        float sc[8][4];
        #pragma unroll
        for (int nt = 0; nt < 8; nt++) {
            sc[nt][0] = sc[nt][1] = sc[nt][2] = sc[nt][3] = 0.f;
            #pragma unroll
            for (int ks = 0; ks < 2; ks++) {
                uint32_t b0 = *(const uint32_t*)&Ks[8 * nt + grp][16 * ks + 2 * tg];
                uint32_t b1 = *(const uint32_t*)&Ks[8 * nt + grp][16 * ks + 2 * tg + 8];
                mma_f16(sc[nt], qa[ks], b0, b1);
            }
        }

        // ---- p = exp2(s); accumulate l partials in fp32; store fp16 P ----
        #pragma unroll
        for (int nt = 0; nt < 8; nt++) {
            float p0 = ex2(sc[nt][0]);
            float p1 = ex2(sc[nt][1]);
            float p2 = ex2(sc[nt][2]);
            float p3 = ex2(sc[nt][3]);
            l0p += p0 + p1;
            l1p += p2 + p3;
            *(__half2*)(Pw + (grp    ) * 72 + 8 * nt + 2 * tg) = __floats2half2_rn(p0, p1);
            *(__half2*)(Pw + (grp + 8) * 72 + 8 * nt + 2 * tg) = __floats2half2_rn(p2, p3);
        }
        __syncwarp();

        // ---- O += P V ----
        #pragma unroll
        for (int ks2 = 0; ks2 < 4; ks2++) {
            uint32_t pa[4];
            pa[0] = *(const uint32_t*)(Pw + (grp    ) * 72 + 16 * ks2 + 2 * tg);
            pa[1] = *(const uint32_t*)(Pw + (grp + 8) * 72 + 16 * ks2 + 2 * tg);
            pa[2] = *(const uint32_t*)(Pw + (grp    ) * 72 + 16 * ks2 + 2 * tg + 8);
            pa[3] = *(const uint32_t*)(Pw + (grp + 8) * 72 + 16 * ks2 + 2 * tg + 8);
            #pragma unroll
            for (int nf = 0; nf < 4; nf++) {
                uint32_t b0 = *(const uint32_t*)&Vs[8 * nf + grp][16 * ks2 + 2 * tg];
                uint32_t b1 = *(const uint32_t*)&Vs[8 * nf + grp][16 * ks2 + 2 * tg + 8];
                mma_f16(o[nf], pa, b0, b1);
            }
        }
    }
    __syncthreads();   // buffers free; Ofs aliases them

    // ---- reduce l across the 4 threads of each row group (once) ----
    l0p += __shfl_xor_sync(0xffffffffu, l0p, 1);
    l0p += __shfl_xor_sync(0xffffffffu, l0p, 2);
    l1p += __shfl_xor_sync(0xffffffffu, l1p, 1);
    l1p += __shfl_xor_sync(0xffffffffu, l1p, 2);

    // ---- epilogue: normalize, stage [f][tok], coalesced fp32 write ----
    float inv0 = 1.0f / l0p, inv1 = 1.0f / l1p;
    float* Ofs = (float*)smraw;   // [32][132]
    #pragma unroll
    for (int nf = 0; nf < 4; nf++) {
        int f0 = 8 * nf + 2 * tg;
        Ofs[(f0    ) * 132 + w * 16 + grp    ] = rtf(o[nf][0] * inv0);
        Ofs[(f0 + 1) * 132 + w * 16 + grp    ] = rtf(o[nf][1] * inv0);
        Ofs[(f0    ) * 132 + w * 16 + grp + 8] = rtf(o[nf][2] * inv1);
        Ofs[(f0 + 1) * 132 + w * 16 + grp + 8] = rtf(o[nf][3] * inv1);
    }
    __syncthreads();
    float* ob = g_att + ((size_t)b * HID + h * DH) * NTOK;
    #pragma unroll
    for (int i = 0; i < 4; i++) {
        int idx4 = tid + 256 * i;
        int f  = idx4 >> 5;
        int tc = (idx4 & 31) * 4;
        float4 v = *(const float4*)&Ofs[f * 132 + tc];
        *(float4*)(ob + (size_t)f * NTOK + n0 + tc) = v;
    }
}

// ================= launch =================
extern "C" void kernel_launch(void* const* d_in, const int* in_sizes, int n_in,
                              void* d_out, int out_size)
{
    const float* x    = (const float*)d_in[0];
    const float* gw   = (const float*)d_in[1];
    const float* gb   = (const float*)d_in[2];
    const float* wqkv = (const float*)d_in[3];
    const float* wout = (const float*)d_in[4];
    const float* bout = (const float*)d_in[5];
    float* out = (float*)d_out;

    float* att = nullptr; cudaGetSymbolAddress((void**)&att, g_att);
    float* xn  = nullptr; cudaGetSymbolAddress((void**)&xn,  g_xn);

    cudaFuncSetAttribute(k_attn, cudaFuncAttributeMaxDynamicSharedMemorySize, SMA_BYTES);

    k_gnstats<<<NB * 32, 256>>>(x, gw, gb);
    k_gemm<NQKV, NC, 1><<<dim3(64, 3, NB), 256>>>(wqkv, xn, nullptr, nullptr);
    k_attn<<<dim3(NTOK / QT, NHEAD, NB), 256, SMA_BYTES>>>();
    k_gemm<NC, HID, 0><<<dim3(64, 2, NB), 256>>>(wout, att, out, bout);
}